// round 7
// baseline (speedup 1.0000x reference)
#include <cuda_runtime.h>
#include <cuda_bf16.h>
#include <math.h>

// Problem constants (fixed by the dataset)
#define NMAX 50000
#define EMAX 800000
#define F_IN 128
#define D1   256
#define D2   128
#define KCL  32

// ---------------- scratch (device globals; no allocation allowed) -------------
__device__ float g_xw [NMAX * D1];     // features @ W1          [N,256]
__device__ float g_H  [NMAX * D1];     // GCN output             [N,256]
__device__ float g_abs[NMAX * D2];     // tanh(H@fc1_W+b)        [N,128]
__device__ float g_S  [NMAX * KCL];    // softmax assignments    [N,32]
__device__ float g_LS [NMAX * KCL];    // L @ S                  [N,32]

__device__ int   g_cnt_in [NMAX];      // in-degree  (by col/target)
__device__ int   g_cnt_out[NMAX];      // out-degree (by row/source)
__device__ int   g_off_in [NMAX + 1];
__device__ int   g_off_out[NMAX + 1];
__device__ int   g_cur_in [NMAX];
__device__ int   g_cur_out[NMAX];
__device__ int   g_csr_in [EMAX];      // sources grouped by target
__device__ int   g_csr_out[EMAX];      // targets grouped by source
__device__ float g_dinv1[NMAX];        // GCN D^-1/2 (with self loop)
__device__ float g_dinv2[NMAX];        // Laplacian D^-1/2 (row degree)

__device__ float g_adj [KCL * KCL];    // S^T @ LS
__device__ float g_sumH[D1];           // column sums of H

// ---------------- small utility kernels ----------------
__global__ void zero_kernel(int n) {
    int i = blockIdx.x * blockDim.x + threadIdx.x;
    if (i < n) { g_cnt_in[i] = 0; g_cnt_out[i] = 0; }
    if (i < KCL * KCL) g_adj[i] = 0.f;
    if (i < D1) g_sumH[i] = 0.f;
}

// edges arrive as INT32 (JAX silently downcasts int64 without x64 mode).
__global__ void count_kernel(const int* __restrict__ edges, int E) {
    int e = blockIdx.x * blockDim.x + threadIdx.x;
    if (e >= E) return;
    int r = edges[e];        // source (row)
    int c = edges[E + e];    // target (col)
    atomicAdd(&g_cnt_in[c], 1);
    atomicAdd(&g_cnt_out[r], 1);
}

__global__ void dinv_kernel(int N) {
    int i = blockIdx.x * blockDim.x + threadIdx.x;
    if (i >= N) return;
    g_dinv1[i] = rsqrtf((float)g_cnt_in[i] + 1.0f);     // self loop included
    int d = g_cnt_out[i];
    g_dinv2[i] = (d > 0) ? rsqrtf((float)d) : 0.0f;
}

// one block per array, exclusive scan (Hillis-Steele chunks of 1024)
__global__ void scan_kernel(int n) {
    const int* cnt = (blockIdx.x == 0) ? g_cnt_in : g_cnt_out;
    int*       off = (blockIdx.x == 0) ? g_off_in : g_off_out;
    __shared__ int sh[1024];
    __shared__ int carry;
    int tid = threadIdx.x;
    if (tid == 0) carry = 0;
    __syncthreads();
    for (int base = 0; base < n; base += 1024) {
        int idx = base + tid;
        int v = (idx < n) ? cnt[idx] : 0;
        sh[tid] = v;
        __syncthreads();
        #pragma unroll
        for (int d = 1; d < 1024; d <<= 1) {
            int t = (tid >= d) ? sh[tid - d] : 0;
            __syncthreads();
            sh[tid] += t;
            __syncthreads();
        }
        int c = carry;
        if (idx < n) off[idx] = c + sh[tid] - v;   // exclusive
        int tot = sh[1023];
        __syncthreads();
        if (tid == 0) carry = c + tot;
        __syncthreads();
    }
    if (tid == 0) off[n] = carry;
}

__global__ void cursor_copy_kernel(int N) {
    int i = blockIdx.x * blockDim.x + threadIdx.x;
    if (i < N) { g_cur_in[i] = g_off_in[i]; g_cur_out[i] = g_off_out[i]; }
}

__global__ void fill_kernel(const int* __restrict__ edges, int E) {
    int e = blockIdx.x * blockDim.x + threadIdx.x;
    if (e >= E) return;
    int r = edges[e];
    int c = edges[E + e];
    int p = atomicAdd(&g_cur_in[c], 1);
    g_csr_in[p] = r;
    int q = atomicAdd(&g_cur_out[r], 1);
    g_csr_out[q] = c;
}

// ---------------- tiled SGEMM: C = op(A@B + bias), row-major ----------------
// EPI: 0 = none, 1 = tanh
template <int EPI>
__global__ void gemm_kernel(const float* __restrict__ A, const float* __restrict__ B,
                            const float* __restrict__ bias, float* __restrict__ C,
                            int M, int N, int K) {
    const int BM = 64, BN = 64, BK = 16;
    __shared__ float As[BK][BM];
    __shared__ float Bs[BK][BN];

    int tid = threadIdx.x;                 // 256
    int tx = tid & 15, ty = tid >> 4;      // 16x16 thread grid, 4x4 microtile
    int rowBase = blockIdx.y * BM;
    int colBase = blockIdx.x * BN;

    int aRow  = tid >> 2;                  // 0..63
    int aCol4 = (tid & 3) * 4;             // 0,4,8,12
    int bRow  = tid >> 4;                  // 0..15
    int bCol4 = (tid & 15) * 4;

    float acc[4][4] = {};
    for (int k0 = 0; k0 < K; k0 += BK) {
        int gr = rowBase + aRow;
        #pragma unroll
        for (int i = 0; i < 4; i++) {
            int gc = k0 + aCol4 + i;
            As[aCol4 + i][aRow] = (gr < M) ? A[(long)gr * K + gc] : 0.f;
        }
        {
            const float4 bv = *(const float4*)&B[(long)(k0 + bRow) * N + colBase + bCol4];
            *(float4*)&Bs[bRow][bCol4] = bv;
        }
        __syncthreads();
        #pragma unroll
        for (int k = 0; k < BK; k++) {
            float4 a4 = *(const float4*)&As[k][ty * 4];
            float4 b4 = *(const float4*)&Bs[k][tx * 4];
            float a[4] = {a4.x, a4.y, a4.z, a4.w};
            float b[4] = {b4.x, b4.y, b4.z, b4.w};
            #pragma unroll
            for (int i = 0; i < 4; i++)
                #pragma unroll
                for (int j = 0; j < 4; j++)
                    acc[i][j] += a[i] * b[j];
        }
        __syncthreads();
    }
    #pragma unroll
    for (int i = 0; i < 4; i++) {
        int r = rowBase + ty * 4 + i;
        if (r >= M) continue;
        #pragma unroll
        for (int j = 0; j < 4; j++) {
            int c = colBase + tx * 4 + j;
            float v = acc[i][j];
            if (bias) v += bias[c];
            if (EPI == 1) v = tanhf(v);
            C[(long)r * N + c] = v;
        }
    }
}

// ---------------- GCN gather: H[i] = b1 + dinv1[i]^2*xw[i] + sum_j dinv1[j]dinv1[i]*xw[j]
__global__ void gcn_gather_kernel(const float* __restrict__ b1, int N) {
    int i = blockIdx.x;            // one node per block
    int t = threadIdx.x;           // 256 = D1
    float di = g_dinv1[i];
    float acc = di * di * g_xw[(long)i * D1 + t];
    int s = g_off_in[i], e = g_off_in[i + 1];
    for (int p = s; p < e; p++) {
        int j = g_csr_in[p];
        acc += di * g_dinv1[j] * g_xw[(long)j * D1 + t];
    }
    g_H[(long)i * D1 + t] = acc + b1[t];
}

// ---------------- fc2 + softmax: one warp per node, lane = cluster k ----------
__global__ void fc2_softmax_kernel(const float* __restrict__ fc2W,
                                   const float* __restrict__ fc2b, int N) {
    int warp = (blockIdx.x * blockDim.x + threadIdx.x) >> 5;
    int lane = threadIdx.x & 31;
    if (warp >= N) return;
    const float* a = g_abs + (long)warp * D2;
    float av[4];
    #pragma unroll
    for (int q = 0; q < 4; q++) av[q] = a[lane + 32 * q];
    float acc = fc2b[lane];
    #pragma unroll
    for (int q = 0; q < 4; q++) {
        #pragma unroll
        for (int kk = 0; kk < 32; kk++) {
            float aval = __shfl_sync(0xffffffffu, av[q], kk);
            acc += aval * fc2W[(q * 32 + kk) * KCL + lane];
        }
    }
    // softmax over 32 lanes
    float m = acc;
    #pragma unroll
    for (int o = 16; o > 0; o >>= 1) m = fmaxf(m, __shfl_xor_sync(0xffffffffu, m, o));
    float ex = __expf(acc - m);
    float sum = ex;
    #pragma unroll
    for (int o = 16; o > 0; o >>= 1) sum += __shfl_xor_sync(0xffffffffu, sum, o);
    g_S[(long)warp * KCL + lane] = ex / sum;
}

// ---------------- LS = S + scatter of -(dinv2[r]dinv2[c]) * S[c] keyed by r ----
__global__ void ls_kernel(int N) {
    int warp = (blockIdx.x * blockDim.x + threadIdx.x) >> 5;
    int lane = threadIdx.x & 31;
    if (warp >= N) return;
    float di = g_dinv2[warp];
    float acc = g_S[(long)warp * KCL + lane];
    int s = g_off_out[warp], e = g_off_out[warp + 1];
    for (int p = s; p < e; p++) {
        int c = g_csr_out[p];
        acc -= di * g_dinv2[c] * g_S[(long)c * KCL + lane];
    }
    g_LS[(long)warp * KCL + lane] = acc;
}

// ---------------- new_adj = S^T @ LS (32x32), partial per block + atomics -----
__global__ void adj_kernel(int N) {
    int tid = threadIdx.x;         // 1024
    int i = tid >> 5, j = tid & 31;
    float acc = 0.f;
    for (int n = blockIdx.x; n < N; n += gridDim.x)
        acc += g_S[(long)n * KCL + i] * g_LS[(long)n * KCL + j];
    atomicAdd(&g_adj[i * KCL + j], acc);
}

// ---------------- column sums of H ----------------
__global__ void sumH_kernel(int N) {
    int t = threadIdx.x;           // 256
    float acc = 0.f;
    for (int n = blockIdx.x; n < N; n += gridDim.x)
        acc += g_H[(long)n * D1 + t];
    atomicAdd(&g_sumH[t], acc);
}

// ---------------- finalize: embedding + pos_penalty ----------------
__global__ void finalize_kernel(float* __restrict__ out, int out_size) {
    int t = threadIdx.x;           // 256
    if (t < D1 && t < out_size) out[t] = g_sumH[t] * (1.0f / KCL);
    if (t < 32) {
        // row L1 norm of new_adj row t
        float rowsum = 0.f;
        #pragma unroll
        for (int c = 0; c < KCL; c++) rowsum += fabsf(g_adj[t * KCL + c]);
        float d = g_adj[t * KCL + t] / fmaxf(rowsum, 1e-12f);
        // MSE(norm_diag broadcast vs eye): column t contributes (K-1)*d^2 + (d-1)^2
        float val = (KCL - 1) * d * d + (d - 1.f) * (d - 1.f);
        #pragma unroll
        for (int o = 16; o > 0; o >>= 1) val += __shfl_xor_sync(0xffffffffu, val, o);
        if (t == 0 && D1 < out_size) out[D1] = val * (1.0f / (KCL * KCL));
    }
}

// ---------------- launch ----------------
extern "C" void kernel_launch(void* const* d_in, const int* in_sizes, int n_in,
                              void* d_out, int out_size) {
    const float* features = (const float*)d_in[0];      // [N,128] f32
    const int*   edges    = (const int*)d_in[1];        // [2,E]  int32 (JAX downcasts int64)
    const float* W1       = (const float*)d_in[2];      // [128,256]
    const float* b1       = (const float*)d_in[3];      // [256]
    const float* fc1W     = (const float*)d_in[4];      // [256,128]
    const float* fc1b     = (const float*)d_in[5];      // [128]
    const float* fc2W     = (const float*)d_in[6];      // [128,32]
    const float* fc2b     = (const float*)d_in[7];      // [32]
    float* out = (float*)d_out;

    int N = in_sizes[0] / F_IN;
    int E = in_sizes[1] / 2;

    // True device addresses of scratch symbols for kernels taking them as params.
    float *p_xw = nullptr, *p_H = nullptr, *p_abs = nullptr;
    cudaGetSymbolAddress((void**)&p_xw,  g_xw);
    cudaGetSymbolAddress((void**)&p_H,   g_H);
    cudaGetSymbolAddress((void**)&p_abs, g_abs);

    // 1. CSR build
    zero_kernel<<<(N + 255) / 256, 256>>>(N);
    count_kernel<<<(E + 255) / 256, 256>>>(edges, E);
    dinv_kernel<<<(N + 255) / 256, 256>>>(N);
    scan_kernel<<<2, 1024>>>(N);
    cursor_copy_kernel<<<(N + 255) / 256, 256>>>(N);
    fill_kernel<<<(E + 255) / 256, 256>>>(edges, E);

    // 2. xw = features @ W1   [N,256]
    {
        dim3 grid(D1 / 64, (N + 63) / 64);
        gemm_kernel<0><<<grid, 256>>>(features, W1, nullptr, p_xw, N, D1, F_IN);
    }

    // 3. GCN aggregation -> H
    gcn_gather_kernel<<<N, D1>>>(b1, N);

    // 4. abstract = tanh(H @ fc1W + fc1b)  [N,128]
    {
        dim3 grid(D2 / 64, (N + 63) / 64);
        gemm_kernel<1><<<grid, 256>>>(p_H, fc1W, fc1b, p_abs, N, D2, D1);
    }

    // 5. S = softmax(abstract @ fc2W + fc2b)  [N,32]
    fc2_softmax_kernel<<<(N * 32 + 255) / 256, 256>>>(fc2W, fc2b, N);

    // 6. LS = L @ S
    ls_kernel<<<(N * 32 + 255) / 256, 256>>>(N);

    // 7. new_adj = S^T @ LS ; sumH
    adj_kernel<<<148, 1024>>>(N);
    sumH_kernel<<<256, 256>>>(N);

    // 8. outputs
    finalize_kernel<<<1, 256>>>(out, out_size);
}